// round 2
// baseline (speedup 1.0000x reference)
#include <cuda_runtime.h>

// Normalized ordinal weights, TRANSPOSED: g_wT[tap][channel], tap-major.
// Thread owning channels [4c..4c+3] loads one float4 per tap at 16B lane
// stride -> fully coalesced L1 accesses (prev layout cost 16 wavefronts/load).
__device__ float g_wT[4 * 128];

__global__ void normw_kernel(const float* __restrict__ w) {
    int c = threadIdx.x;
    if (c < 128) {
        float a = w[c * 4 + 0];
        float b = w[c * 4 + 1];
        float d = w[c * 4 + 2];
        float e = w[c * 4 + 3];
        a = (a >= 0.0f) ? a : 0.0f;
        b = (b >= 0.0f) ? b : 0.0f;
        d = (d >= 0.0f) ? d : 0.0f;
        e = (e >= 0.0f) ? e : 0.0f;
        float inv = 1.0f / (a + b + d + e);
        g_wT[0 * 128 + c] = a * inv;
        g_wT[1 * 128 + c] = b * inv;
        g_wT[2 * 128 + c] = d * inv;
        g_wT[3 * 128 + c] = e * inv;
    }
}

// Odd-even transposition sort (descending) of 4 values + weighted sum.
// Network (reference, n=4): (0,1),(2,3) / (1,2) / (0,1),(2,3) / (1,2)
__device__ __forceinline__ float sort4_dot(float s0, float s1, float s2, float s3,
                                           float w0, float w1, float w2, float w3) {
    float t;
    t = fmaxf(s0, s1); s1 = fminf(s0, s1); s0 = t;
    t = fmaxf(s2, s3); s3 = fminf(s2, s3); s2 = t;
    t = fmaxf(s1, s2); s2 = fminf(s1, s2); s1 = t;
    t = fmaxf(s0, s1); s1 = fminf(s0, s1); s0 = t;
    t = fmaxf(s2, s3); s3 = fminf(s2, s3); s2 = t;
    t = fmaxf(s1, s2); s2 = fminf(s1, s2); s1 = t;
    return s0 * w0 + s1 * w1 + s2 * w2 + s3 * w3;
}

// Geometry
#define N_   32
#define H_   112
#define W_   112
#define C_   128
#define HO_  56
#define WO_  56
#define WO2_ (WO_ / 2)           // 28 output-column pairs
#define C4_  (C_ / 4)            // 32 float4 per channel row (== warp width)
#define ROW4 (W_ * C4_)          // input row stride in float4 = 3584
#define NV2  (N_ * HO_ * WO2_ * C4_)  // threads (2 outputs each) = 1,605,632

__global__ void __launch_bounds__(256)
ordpool_kernel(const float4* __restrict__ x, float4* __restrict__ out) {
    int v = blockIdx.x * blockDim.x + threadIdx.x;
    if (v >= NV2) return;

    int c4 = v & (C4_ - 1);
    int r  = v >> 5;
    int wo2 = r % WO2_;
    r /= WO2_;
    int ho = r % HO_;
    int n  = r / HO_;

    // Two adjacent 2x2 windows -> one contiguous 4-column input span.
    int base = ((n * H_ + 2 * ho) * W_ + 4 * wo2) * C4_ + c4;

    // 8 independent loads front-batched (MLP_p1 = 8).
    float4 a0 = x[base];
    float4 a1 = x[base + C4_];
    float4 a2 = x[base + 2 * C4_];
    float4 a3 = x[base + 3 * C4_];
    float4 b0 = x[base + ROW4];
    float4 b1 = x[base + ROW4 + C4_];
    float4 b2 = x[base + ROW4 + 2 * C4_];
    float4 b3 = x[base + ROW4 + 3 * C4_];

    // Coalesced weight loads (tap-major): lane stride 16B.
    const float4* __restrict__ gw = (const float4*)g_wT;
    float4 w0 = gw[0 * C4_ + c4];
    float4 w1 = gw[1 * C4_ + c4];
    float4 w2 = gw[2 * C4_ + c4];
    float4 w3 = gw[3 * C4_ + c4];

    // Window 0: cols (0,1); window 1: cols (2,3).
    float4 o0, o1;
    o0.x = sort4_dot(a0.x, a1.x, b0.x, b1.x, w0.x, w1.x, w2.x, w3.x);
    o0.y = sort4_dot(a0.y, a1.y, b0.y, b1.y, w0.y, w1.y, w2.y, w3.y);
    o0.z = sort4_dot(a0.z, a1.z, b0.z, b1.z, w0.z, w1.z, w2.z, w3.z);
    o0.w = sort4_dot(a0.w, a1.w, b0.w, b1.w, w0.w, w1.w, w2.w, w3.w);

    o1.x = sort4_dot(a2.x, a3.x, b2.x, b3.x, w0.x, w1.x, w2.x, w3.x);
    o1.y = sort4_dot(a2.y, a3.y, b2.y, b3.y, w0.y, w1.y, w2.y, w3.y);
    o1.z = sort4_dot(a2.z, a3.z, b2.z, b3.z, w0.z, w1.z, w2.z, w3.z);
    o1.w = sort4_dot(a2.w, a3.w, b2.w, b3.w, w0.w, w1.w, w2.w, w3.w);

    int oidx = ((n * HO_ + ho) * WO_ + 2 * wo2) * C4_ + c4;
    out[oidx]       = o0;
    out[oidx + C4_] = o1;
}

extern "C" void kernel_launch(void* const* d_in, const int* in_sizes, int n_in,
                              void* d_out, int out_size) {
    const float* x = (const float*)d_in[0];
    const float* w = (const float*)d_in[1];
    float* out = (float*)d_out;

    normw_kernel<<<1, 128>>>(w);
    ordpool_kernel<<<(NV2 + 255) / 256, 256>>>((const float4*)x, (float4*)out);
}

// round 5
// speedup vs baseline: 1.1031x; 1.1031x over previous
#include <cuda_runtime.h>

// Geometry
#define N_   32
#define H_   112
#define W_   112
#define C_   128
#define HO_  56
#define WO_  56
#define C4_  (C_ / 4)                 // 32 float4 per channel row (== warp width)
#define ROW4 (W_ * C4_)               // input row stride in float4 = 3584
#define NV   (N_ * HO_ * WO_ * C4_)   // total output float4 = 3,211,264 (divisible by 256)

// Odd-even transposition sort (descending) of 4 values + weighted sum.
// Network (reference, n=4): (0,1),(2,3) / (1,2) / (0,1),(2,3) / (1,2)
__device__ __forceinline__ float sort4_dot(float s0, float s1, float s2, float s3,
                                           float w0, float w1, float w2, float w3) {
    float t;
    t = fmaxf(s0, s1); s1 = fminf(s0, s1); s0 = t;
    t = fmaxf(s2, s3); s3 = fminf(s2, s3); s2 = t;
    t = fmaxf(s1, s2); s2 = fminf(s1, s2); s1 = t;
    t = fmaxf(s0, s1); s1 = fminf(s0, s1); s0 = t;
    t = fmaxf(s2, s3); s3 = fminf(s2, s3); s2 = t;
    t = fmaxf(s1, s2); s2 = fminf(s1, s2); s1 = t;
    return s0 * w0 + s1 * w1 + s2 * w2 + s3 * w3;
}

__global__ void __launch_bounds__(256)
ordpool_kernel(const float4* __restrict__ x, const float* __restrict__ wraw,
               float4* __restrict__ out) {
    // Tap-major normalized weights: sw[tap][channel]. 2 KB.
    __shared__ __align__(16) float sw[4][C_];

    int v = blockIdx.x * 256 + threadIdx.x;   // grid*block == NV exactly, no tail

    int c4 = v & (C4_ - 1);
    int r  = v >> 5;
    int wo = r % WO_;
    r /= WO_;
    int ho = r % HO_;
    int n  = r / HO_;

    int base = ((n * H_ + 2 * ho) * W_ + 2 * wo) * C4_ + c4;

    // Issue the 4 independent data loads FIRST so they are in flight
    // while the weight prologue runs.
    float4 a00 = x[base];
    float4 a01 = x[base + C4_];
    float4 a10 = x[base + ROW4];
    float4 a11 = x[base + ROW4 + C4_];

    // Per-block weight normalization (threads 0..127, one channel each).
    // wraw layout is [C][4] -> one float4 per channel.
    if (threadIdx.x < C_) {
        int c = threadIdx.x;
        float4 wv = ((const float4*)wraw)[c];
        float a = (wv.x >= 0.0f) ? wv.x : 0.0f;
        float b = (wv.y >= 0.0f) ? wv.y : 0.0f;
        float d = (wv.z >= 0.0f) ? wv.z : 0.0f;
        float e = (wv.w >= 0.0f) ? wv.w : 0.0f;
        float inv = 1.0f / (a + b + d + e);
        sw[0][c] = a * inv;
        sw[1][c] = b * inv;
        sw[2][c] = d * inv;
        sw[3][c] = e * inv;
    }
    __syncthreads();

    // Conflict-free LDS.128: lane c4 reads 16B at consecutive addresses.
    float4 w0 = *(const float4*)&sw[0][4 * c4];
    float4 w1 = *(const float4*)&sw[1][4 * c4];
    float4 w2 = *(const float4*)&sw[2][4 * c4];
    float4 w3 = *(const float4*)&sw[3][4 * c4];

    float4 o;
    o.x = sort4_dot(a00.x, a01.x, a10.x, a11.x, w0.x, w1.x, w2.x, w3.x);
    o.y = sort4_dot(a00.y, a01.y, a10.y, a11.y, w0.y, w1.y, w2.y, w3.y);
    o.z = sort4_dot(a00.z, a01.z, a10.z, a11.z, w0.z, w1.z, w2.z, w3.z);
    o.w = sort4_dot(a00.w, a01.w, a10.w, a11.w, w0.w, w1.w, w2.w, w3.w);

    out[v] = o;
}

extern "C" void kernel_launch(void* const* d_in, const int* in_sizes, int n_in,
                              void* d_out, int out_size) {
    const float* x = (const float*)d_in[0];
    const float* w = (const float*)d_in[1];
    float* out = (float*)d_out;

    ordpool_kernel<<<NV / 256, 256>>>((const float4*)x, w, (float4*)out);
}

// round 6
// speedup vs baseline: 1.1040x; 1.0008x over previous
#include <cuda_runtime.h>

// Geometry
#define N_   32
#define H_   112
#define W_   112
#define C_   128
#define HO_  56
#define WO_  56
#define C4_  (C_ / 4)                 // 32 float4 per channel row (== warp width)
#define ROW4 (W_ * C4_)               // input row stride in float4 = 3584
#define PLANE_BLKS ((WO_ * C4_) / 256)  // 7 blocks cover one (wo, c4) plane

// Odd-even transposition sort (descending) of 4 values + weighted sum.
// Network (reference, n=4): (0,1),(2,3) / (1,2) / (0,1),(2,3) / (1,2)
__device__ __forceinline__ float sort4_dot(float s0, float s1, float s2, float s3,
                                           float w0, float w1, float w2, float w3) {
    float t;
    t = fmaxf(s0, s1); s1 = fminf(s0, s1); s0 = t;
    t = fmaxf(s2, s3); s3 = fminf(s2, s3); s2 = t;
    t = fmaxf(s1, s2); s2 = fminf(s1, s2); s1 = t;
    t = fmaxf(s0, s1); s1 = fminf(s0, s1); s0 = t;
    t = fmaxf(s2, s3); s3 = fminf(s2, s3); s2 = t;
    t = fmaxf(s1, s2); s2 = fminf(s1, s2); s1 = t;
    return s0 * w0 + s1 * w1 + s2 * w2 + s3 * w3;
}

__global__ void __launch_bounds__(256)
ordpool_kernel(const float4* __restrict__ x, const float* __restrict__ wraw,
               float4* __restrict__ out) {
    // Tap-major normalized weights: sw[tap][channel]. 2 KB.
    __shared__ __align__(16) float sw[4][C_];

    // 3D grid: x covers (wo, c4) plane with shifts/masks only, y = ho, z = n.
    int t  = blockIdx.x * 256 + threadIdx.x;   // 0 .. 1791
    int c4 = t & (C4_ - 1);
    int wo = t >> 5;                            // 0 .. 55
    int ho = blockIdx.y;
    int n  = blockIdx.z;

    int base = ((n * H_ + 2 * ho) * W_ + 2 * wo) * C4_ + c4;

    // Issue the 4 independent data loads FIRST (in flight during the
    // weight prologue). Streaming hint: every input byte is read exactly once.
    float4 a00 = __ldcs(&x[base]);
    float4 a01 = __ldcs(&x[base + C4_]);
    float4 a10 = __ldcs(&x[base + ROW4]);
    float4 a11 = __ldcs(&x[base + ROW4 + C4_]);

    // Per-block weight normalization (threads 0..127, one channel each).
    // wraw layout is [C][4] -> one float4 per channel.
    if (threadIdx.x < C_) {
        int c = threadIdx.x;
        float4 wv = ((const float4*)wraw)[c];
        float a = (wv.x >= 0.0f) ? wv.x : 0.0f;
        float b = (wv.y >= 0.0f) ? wv.y : 0.0f;
        float d = (wv.z >= 0.0f) ? wv.z : 0.0f;
        float e = (wv.w >= 0.0f) ? wv.w : 0.0f;
        float inv = 1.0f / (a + b + d + e);
        sw[0][c] = a * inv;
        sw[1][c] = b * inv;
        sw[2][c] = d * inv;
        sw[3][c] = e * inv;
    }
    __syncthreads();

    // Conflict-free LDS.128: lane c4 reads 16B at consecutive addresses.
    float4 w0 = *(const float4*)&sw[0][4 * c4];
    float4 w1 = *(const float4*)&sw[1][4 * c4];
    float4 w2 = *(const float4*)&sw[2][4 * c4];
    float4 w3 = *(const float4*)&sw[3][4 * c4];

    float4 o;
    o.x = sort4_dot(a00.x, a01.x, a10.x, a11.x, w0.x, w1.x, w2.x, w3.x);
    o.y = sort4_dot(a00.y, a01.y, a10.y, a11.y, w0.y, w1.y, w2.y, w3.y);
    o.z = sort4_dot(a00.z, a01.z, a10.z, a11.z, w0.z, w1.z, w2.z, w3.z);
    o.w = sort4_dot(a00.w, a01.w, a10.w, a11.w, w0.w, w1.w, w2.w, w3.w);

    // Streaming store: output is written once, never re-read by this kernel.
    int oidx = ((n * HO_ + ho) * WO_ + wo) * C4_ + c4;
    __stcs(&out[oidx], o);
}

extern "C" void kernel_launch(void* const* d_in, const int* in_sizes, int n_in,
                              void* d_out, int out_size) {
    const float* x = (const float*)d_in[0];
    const float* w = (const float*)d_in[1];
    float* out = (float*)d_out;

    dim3 grid(PLANE_BLKS, HO_, N_);   // (7, 56, 32) = 12544 blocks
    ordpool_kernel<<<grid, 256>>>((const float4*)x, w, (float4*)out);
}